// round 6
// baseline (speedup 1.0000x reference)
#include <cuda_runtime.h>
#include <math.h>

#define N_NODES 10000
#define N_EDGES 320000
#define WARPS 8
#define EPW 8              // edges per warp
#define EPB 64             // edges per block per iteration

// output region offsets in floats
#define OFF_NODE_EMB   0L
#define OFF_EDGE_EMB   80000L
#define OFF_RECON_NODE 2640000L
#define OFF_RECON_EDGE 3280000L
#define OFF_ADJ        13520000L
#define OFF_COORD      113520000L

__device__ float g_A[N_NODES * 128];          // nf @ W1[0:64]  + b1
__device__ float g_B[N_NODES * 128];          // nf @ W1[64:128]
__device__ float g_hn[N_NODES * 128];         // relu(node layer-1)
__device__ float g_agg[N_NODES * 32];         // segment_sum(edge_out)
__device__ float g_emb[N_NODES * 8];          // node_emb copy for adj kernel
__device__ float g_r[N_NODES];                // ||node_emb||^2

// ---------------------------------------------------------------------------
__global__ void k_init(const float* __restrict__ coords, float* __restrict__ out) {
    int i = blockIdx.x * blockDim.x + threadIdx.x;
    if (i < N_NODES * 32) g_agg[i] = 0.f;
    if (i < N_NODES * 3)  out[OFF_COORD + i] = coords[i];
}

// ---------------------------------------------------------------------------
__global__ __launch_bounds__(128) void k_nodeproj(int which,
                                                  const float* __restrict__ nf,
                                                  const float* __restrict__ w,   // [64,128]
                                                  const float* __restrict__ b) {
    __shared__ float ws[64 * 128];
    __shared__ float xs[64];
    float* dst = which ? g_B : g_A;
    int tid = threadIdx.x;
    for (int i = tid; i < 64 * 128; i += 128) ws[i] = w[i];
    float bias = b ? b[tid] : 0.f;
    __syncthreads();
    for (int n = blockIdx.x; n < N_NODES; n += gridDim.x) {
        if (tid < 64) xs[tid] = nf[n * 64 + tid];
        __syncthreads();
        float acc = bias;
#pragma unroll
        for (int f = 0; f < 64; f++) acc = fmaf(xs[f], ws[f * 128 + tid], acc);
        dst[n * 128 + tid] = acc;
        __syncthreads();
    }
}

// ---------------------------------------------------------------------------
// K2: warp-autonomous fused edge kernel.  Each warp owns 8 edges end-to-end.
// Layer1: thread = k-quad (kg=lane), accumulates 8 edges x 4 k.
// Layer2/epilogue: thread = (jq = lane>>3, e = lane&7): one edge, 8 j's.
// No __syncthreads in the main loop.
// ---------------------------------------------------------------------------
__global__ __launch_bounds__(256, 3) void k_edge_fused(
        const float* __restrict__ ew1,  // [161,128]
        const float* __restrict__ ew2, const float* __restrict__ eb2,
        const float* __restrict__ cw1, const float* __restrict__ cb1,
        const float* __restrict__ cw2,
        const float* __restrict__ few, const float* __restrict__ feb,
        const float* __restrict__ dew, const float* __restrict__ deb,
        const int* __restrict__ ei, const float* __restrict__ ea,
        const float* __restrict__ coords,
        float* __restrict__ out) {
    __shared__ __align__(16) float easT[WARPS][32][12];   // [kk][e], padded
    __shared__ __align__(16) float hs[WARPS][EPW][132];   // [e][k], padded
    __shared__ float s_b2[32], s_fcb[8], s_deb[32], s_misc[4];

    int tid = threadIdx.x;
    int w = tid >> 5, lane = tid & 31;
    int kg = lane;                       // layer-1 k-quad index
    int e_l = lane & 7, jq = lane >> 3;  // layer-2 mapping

    if (tid < 32) { s_b2[tid] = eb2[tid]; s_deb[tid] = deb[tid]; }
    if (tid < 8)  s_fcb[tid] = feb[tid];
    if (tid == 0) { s_misc[0] = cb1[0]; s_misc[1] = cb1[1]; s_misc[2] = cw2[0]; s_misc[3] = cw2[1]; }
    __syncthreads();

    float4 w1r4 = __ldg((const float4*)(ew1 + 160 * 128 + kg * 4));

    const long stride = (long)gridDim.x * EPB;
    for (long base = (long)blockIdx.x * EPB + w * EPW; base < N_EDGES; base += stride) {
        // ---- stage: lanes 0..7 hold edge meta in registers ----
        int myrow = 0, mycol = 0;
        float md0 = 0.f, md1 = 0.f, md2 = 0.f, mrad = 0.f;
        if (lane < EPW) {
            long e = base + lane;
            myrow = ei[e]; mycol = ei[N_EDGES + e];
            md0 = coords[myrow * 3 + 0] - coords[mycol * 3 + 0];
            md1 = coords[myrow * 3 + 1] - coords[mycol * 3 + 1];
            md2 = coords[myrow * 3 + 2] - coords[mycol * 3 + 2];
            mrad = md0 * md0 + md1 * md1 + md2 * md2;
        }
        __syncwarp();   // prior iteration fully done before overwriting easT/hs

        // ---- ea transpose into easT[kk][e] ----
#pragma unroll
        for (int t = 0; t < 2; t++) {
            int v = lane + t * 32;
            int e = v >> 3, c4 = v & 7;
            float4 x = __ldg((const float4*)(ea + (base + e) * 32 + c4 * 4));
            easT[w][c4 * 4 + 0][e] = x.x;
            easT[w][c4 * 4 + 1][e] = x.y;
            easT[w][c4 * 4 + 2][e] = x.z;
            easT[w][c4 * 4 + 3][e] = x.w;
        }
        __syncwarp();

        // ---- layer 1: acc[e] (float4 over k-quad) ----
        float4 acc[EPW];
#pragma unroll
        for (int i = 0; i < EPW; i++) {
            int r   = __shfl_sync(0xffffffffu, myrow, i);
            int c   = __shfl_sync(0xffffffffu, mycol, i);
            float rad = __shfl_sync(0xffffffffu, mrad, i);
            float4 a = *(const float4*)(g_A + (long)r * 128 + kg * 4);
            float4 b = *(const float4*)(g_B + (long)c * 128 + kg * 4);
            acc[i].x = a.x + b.x + rad * w1r4.x;
            acc[i].y = a.y + b.y + rad * w1r4.y;
            acc[i].z = a.z + b.z + rad * w1r4.z;
            acc[i].w = a.w + b.w + rad * w1r4.w;
        }
#pragma unroll
        for (int kk = 0; kk < 32; kk++) {
            float4 wv = __ldg((const float4*)(ew1 + (128 + kk) * 128 + kg * 4));
            float4 a0 = *(const float4*)&easT[w][kk][0];
            float4 a1 = *(const float4*)&easT[w][kk][4];
            float av[8] = {a0.x, a0.y, a0.z, a0.w, a1.x, a1.y, a1.z, a1.w};
#pragma unroll
            for (int i = 0; i < EPW; i++) {
                acc[i].x = fmaf(av[i], wv.x, acc[i].x);
                acc[i].y = fmaf(av[i], wv.y, acc[i].y);
                acc[i].z = fmaf(av[i], wv.z, acc[i].z);
                acc[i].w = fmaf(av[i], wv.w, acc[i].w);
            }
        }
#pragma unroll
        for (int i = 0; i < EPW; i++) {
            float4 hv;
            hv.x = fmaxf(acc[i].x, 0.f); hv.y = fmaxf(acc[i].y, 0.f);
            hv.z = fmaxf(acc[i].z, 0.f); hv.w = fmaxf(acc[i].w, 0.f);
            *(float4*)&hs[w][i][kg * 4] = hv;
        }
        __syncwarp();

        // ---- layer 2: lane (jq,e): out[e][jq*8 .. jq*8+7] ----
        float acc2[8] = {0, 0, 0, 0, 0, 0, 0, 0};
        const float* hrow = &hs[w][e_l][0];
        const float* w2p = ew2 + jq * 8;
#pragma unroll 8
        for (int kq = 0; kq < 32; kq++) {
            float4 a4 = *(const float4*)(hrow + kq * 4);
            float avv[4] = {a4.x, a4.y, a4.z, a4.w};
#pragma unroll
            for (int t = 0; t < 4; t++) {
                int kk = kq * 4 + t;
                float4 b0 = __ldg((const float4*)(w2p + kk * 32));
                float4 b1 = __ldg((const float4*)(w2p + kk * 32 + 4));
                float av = avv[t];
                acc2[0] = fmaf(av, b0.x, acc2[0]);
                acc2[1] = fmaf(av, b0.y, acc2[1]);
                acc2[2] = fmaf(av, b0.z, acc2[2]);
                acc2[3] = fmaf(av, b0.w, acc2[3]);
                acc2[4] = fmaf(av, b1.x, acc2[4]);
                acc2[5] = fmaf(av, b1.y, acc2[5]);
                acc2[6] = fmaf(av, b1.z, acc2[6]);
                acc2[7] = fmaf(av, b1.w, acc2[7]);
            }
        }

        // ---- epilogue ----
        int   row  = __shfl_sync(0xffffffffu, myrow, e_l);
        float d0e  = __shfl_sync(0xffffffffu, md0, e_l);
        float d1e  = __shfl_sync(0xffffffffu, md1, e_l);
        float d2e  = __shfl_sync(0xffffffffu, md2, e_l);
        float rade = __shfl_sync(0xffffffffu, mrad, e_l);
        long e = base + e_l;

        float ov[8];
#pragma unroll
        for (int jr = 0; jr < 8; jr++) {
            ov[jr] = acc2[jr] + s_b2[jq * 8 + jr];
            atomicAdd(&g_agg[row * 32 + jq * 8 + jr], ov[jr]);
        }
        float p[10] = {0, 0, 0, 0, 0, 0, 0, 0, 0, 0};
#pragma unroll
        for (int jr = 0; jr < 8; jr++) {
            int j = jq * 8 + jr;
            float4 f0 = __ldg((const float4*)(few + j * 8));
            float4 f1 = __ldg((const float4*)(few + j * 8 + 4));
            p[0] = fmaf(ov[jr], f0.x, p[0]); p[1] = fmaf(ov[jr], f0.y, p[1]);
            p[2] = fmaf(ov[jr], f0.z, p[2]); p[3] = fmaf(ov[jr], f0.w, p[3]);
            p[4] = fmaf(ov[jr], f1.x, p[4]); p[5] = fmaf(ov[jr], f1.y, p[5]);
            p[6] = fmaf(ov[jr], f1.z, p[6]); p[7] = fmaf(ov[jr], f1.w, p[7]);
            float2 cc = __ldg((const float2*)(cw1 + j * 2));
            p[8] = fmaf(ov[jr], cc.x, p[8]); p[9] = fmaf(ov[jr], cc.y, p[9]);
        }
        // reduce across the 4 jq-lanes of this edge (xor 8, 16)
#pragma unroll
        for (int off = 8; off <= 16; off <<= 1) {
#pragma unroll
            for (int r = 0; r < 10; r++) p[r] += __shfl_xor_sync(0xffffffffu, p[r], off);
        }
        float er[8];
#pragma unroll
        for (int r = 0; r < 8; r++) er[r] = p[r] + s_fcb[r];
        if (jq == 0) {
            float4* o = (float4*)(out + OFF_EDGE_EMB + e * 8);
            o[0] = make_float4(er[0], er[1], er[2], er[3]);
            o[1] = make_float4(er[4], er[5], er[6], er[7]);
        }
        // recon_edge: this lane's 8 j's
        float4 rec0, rec1;
        rec0 = make_float4(s_deb[jq * 8 + 0], s_deb[jq * 8 + 1], s_deb[jq * 8 + 2], s_deb[jq * 8 + 3]);
        rec1 = make_float4(s_deb[jq * 8 + 4], s_deb[jq * 8 + 5], s_deb[jq * 8 + 6], s_deb[jq * 8 + 7]);
#pragma unroll
        for (int r = 0; r < 8; r++) {
            float4 dv0 = __ldg((const float4*)(dew + r * 32 + jq * 8));
            float4 dv1 = __ldg((const float4*)(dew + r * 32 + jq * 8 + 4));
            rec0.x = fmaf(er[r], dv0.x, rec0.x); rec0.y = fmaf(er[r], dv0.y, rec0.y);
            rec0.z = fmaf(er[r], dv0.z, rec0.z); rec0.w = fmaf(er[r], dv0.w, rec0.w);
            rec1.x = fmaf(er[r], dv1.x, rec1.x); rec1.y = fmaf(er[r], dv1.y, rec1.y);
            rec1.z = fmaf(er[r], dv1.z, rec1.z); rec1.w = fmaf(er[r], dv1.w, rec1.w);
        }
        ((float4*)(out + OFF_RECON_EDGE + e * 32 + jq * 8))[0] = rec0;
        ((float4*)(out + OFF_RECON_EDGE + e * 32 + jq * 8 + 4))[0] = rec1;
        // coord update (3 components) by the jq==0 lane of each edge
        if (jq == 0) {
            float wz = fmaxf(p[8] + s_misc[0], 0.f) * s_misc[2] +
                       fmaxf(p[9] + s_misc[1], 0.f) * s_misc[3];
            float inv = 1.0f / (sqrtf(rade) + 1.0f);
            float s = inv * wz;
            atomicAdd(out + OFF_COORD + row * 3 + 0, d0e * s);
            atomicAdd(out + OFF_COORD + row * 3 + 1, d1e * s);
            atomicAdd(out + OFF_COORD + row * 3 + 2, d2e * s);
        }
    }
}

// ---------------------------------------------------------------------------
__global__ __launch_bounds__(256) void k_node_h(const float* __restrict__ nw1,  // [99,128]
                                                const float* __restrict__ nb1,
                                                const float* __restrict__ nf,
                                                const float* __restrict__ outc) {
    int tid = threadIdx.x;
    int k = tid & 127, slot = tid >> 7, lane = tid & 31;
    float bias = nb1[k];
    float wc0 = nw1[96 * 128 + k], wc1 = nw1[97 * 128 + k], wc2 = nw1[98 * 128 + k];
    for (int n0 = blockIdx.x * 2; n0 < N_NODES; n0 += gridDim.x * 2) {
        int n = n0 + slot;
        float xa = nf[n * 64 + lane];
        float xb = nf[n * 64 + 32 + lane];
        float xc = g_agg[n * 32 + lane];
        float h = bias;
#pragma unroll
        for (int t = 0; t < 32; t++)
            h = fmaf(__shfl_sync(0xffffffffu, xa, t), __ldg(nw1 + t * 128 + k), h);
#pragma unroll
        for (int t = 0; t < 32; t++)
            h = fmaf(__shfl_sync(0xffffffffu, xb, t), __ldg(nw1 + (32 + t) * 128 + k), h);
#pragma unroll
        for (int t = 0; t < 32; t++)
            h = fmaf(__shfl_sync(0xffffffffu, xc, t), __ldg(nw1 + (64 + t) * 128 + k), h);
        h = fmaf(outc[n * 3 + 0], wc0, h);
        h = fmaf(outc[n * 3 + 1], wc1, h);
        h = fmaf(outc[n * 3 + 2], wc2, h);
        g_hn[n * 128 + k] = fmaxf(h, 0.f);
    }
}

// ---------------------------------------------------------------------------
__global__ __launch_bounds__(256) void k_node_out(
        const float* __restrict__ nw2, const float* __restrict__ nb2,
        const float* __restrict__ fnw, const float* __restrict__ fnb,
        const float* __restrict__ dnw, const float* __restrict__ dnb,
        float* __restrict__ out) {
    __shared__ float ps[4][2][8];
    int tid = threadIdx.x;
    int slot = tid >> 6, jj = tid & 63, half = (tid >> 5) & 1, lane = tid & 31;
    float bias = nb2[jj];
    for (int n0 = blockIdx.x * 4; n0 < N_NODES; n0 += gridDim.x * 4) {
        int n = n0 + slot;
        const float* hrow = g_hn + n * 128;
        float acc = bias;
#pragma unroll 8
        for (int kk = 0; kk < 128; kk++)
            acc = fmaf(__ldg(hrow + kk), __ldg(nw2 + kk * 64 + jj), acc);
        float p[8];
#pragma unroll
        for (int r = 0; r < 8; r++) p[r] = acc * __ldg(fnw + jj * 8 + r);
#pragma unroll
        for (int off = 16; off > 0; off >>= 1) {
#pragma unroll
            for (int r = 0; r < 8; r++) p[r] += __shfl_xor_sync(0xffffffffu, p[r], off);
        }
        if (lane == 0) {
#pragma unroll
            for (int r = 0; r < 8; r++) ps[slot][half][r] = p[r];
        }
        __syncthreads();
        float er[8];
#pragma unroll
        for (int r = 0; r < 8; r++) er[r] = ps[slot][0][r] + ps[slot][1][r] + __ldg(fnb + r);
        if (jj == 0) {
            float4 v0 = make_float4(er[0], er[1], er[2], er[3]);
            float4 v1 = make_float4(er[4], er[5], er[6], er[7]);
            ((float4*)(out + OFF_NODE_EMB + (long)n * 8))[0] = v0;
            ((float4*)(out + OFF_NODE_EMB + (long)n * 8))[1] = v1;
            ((float4*)(g_emb + n * 8))[0] = v0;
            ((float4*)(g_emb + n * 8))[1] = v1;
            float rr = 0.f;
#pragma unroll
            for (int r = 0; r < 8; r++) rr = fmaf(er[r], er[r], rr);
            g_r[n] = rr;
        }
        float rec = __ldg(dnb + jj);
#pragma unroll
        for (int r = 0; r < 8; r++) rec = fmaf(er[r], __ldg(dnw + r * 64 + jj), rec);
        out[OFF_RECON_NODE + (long)n * 64 + jj] = rec;
        __syncthreads();
    }
}

// ---------------------------------------------------------------------------
__global__ __launch_bounds__(256) void k_adj(float* __restrict__ out) {
    int tid = threadIdx.x;
    int j0 = blockIdx.x * 1024 + tid * 4;
    float ej[4][8], rj[4];
#pragma unroll
    for (int q = 0; q < 4; q++) {
        int jx = j0 + q;
        if (jx < N_NODES) {
            float4 a = ((const float4*)(g_emb + jx * 8))[0];
            float4 b = ((const float4*)(g_emb + jx * 8))[1];
            ej[q][0] = a.x; ej[q][1] = a.y; ej[q][2] = a.z; ej[q][3] = a.w;
            ej[q][4] = b.x; ej[q][5] = b.y; ej[q][6] = b.z; ej[q][7] = b.w;
            rj[q] = g_r[jx];
        } else {
#pragma unroll
            for (int r = 0; r < 8; r++) ej[q][r] = 0.f;
            rj[q] = 0.f;
        }
    }
    int ibase = blockIdx.y * 16;
    for (int ii = 0; ii < 16; ii++) {
        int i = ibase + ii;
        float4 a = ((const float4*)(g_emb + i * 8))[0];
        float4 b = ((const float4*)(g_emb + i * 8))[1];
        float eiv[8] = {a.x, a.y, a.z, a.w, b.x, b.y, b.z, b.w};
        float ri = g_r[i];
        float res[4];
#pragma unroll
        for (int q = 0; q < 4; q++) {
            float dot = 0.f;
#pragma unroll
            for (int r = 0; r < 8; r++) dot = fmaf(eiv[r], ej[q][r], dot);
            float d2 = ri + rj[q] - 2.f * dot;
            float ex = __expf(1.f - 3.f * d2);
            float v = __fdividef(1.f, 1.f + ex);
            res[q] = (j0 + q == i) ? 0.f : v;
        }
        if (j0 < N_NODES) {
            __stcs((float4*)(out + OFF_ADJ + (long)i * N_NODES + j0),
                   make_float4(res[0], res[1], res[2], res[3]));
        }
    }
}

// ---------------------------------------------------------------------------
extern "C" void kernel_launch(void* const* d_in, const int* in_sizes, int n_in,
                              void* d_out, int out_size) {
    const float* nf     = (const float*)d_in[0];
    const int*   ei     = (const int*)  d_in[1];
    const float* ea     = (const float*)d_in[2];
    const float* coords = (const float*)d_in[3];
    const float* ew1    = (const float*)d_in[4];
    const float* eb1    = (const float*)d_in[5];
    const float* ew2    = (const float*)d_in[6];
    const float* eb2    = (const float*)d_in[7];
    const float* cw1    = (const float*)d_in[8];
    const float* cb1    = (const float*)d_in[9];
    const float* cw2    = (const float*)d_in[10];
    const float* nw1    = (const float*)d_in[11];
    const float* nb1    = (const float*)d_in[12];
    const float* nw2    = (const float*)d_in[13];
    const float* nb2    = (const float*)d_in[14];
    const float* fnw    = (const float*)d_in[15];
    const float* fnb    = (const float*)d_in[16];
    const float* few    = (const float*)d_in[17];
    const float* feb    = (const float*)d_in[18];
    const float* dnw    = (const float*)d_in[19];
    const float* dnb    = (const float*)d_in[20];
    const float* dew    = (const float*)d_in[21];
    const float* deb    = (const float*)d_in[22];
    float* out = (float*)d_out;

    k_init<<<(N_NODES * 32 + 255) / 256, 256>>>(coords, out);
    k_nodeproj<<<592, 128>>>(0, nf, ew1, eb1);
    k_nodeproj<<<592, 128>>>(1, nf, ew1 + 64 * 128, 0);
    k_edge_fused<<<592, 256>>>(ew1, ew2, eb2, cw1, cb1, cw2, few, feb, dew, deb,
                               ei, ea, coords, out);
    k_node_h<<<592, 256>>>(nw1, nb1, nf, out + OFF_COORD);
    k_node_out<<<592, 256>>>(nw2, nb2, fnw, fnb, dnw, dnb, out);
    dim3 gadj((N_NODES + 1023) / 1024, N_NODES / 16);
    k_adj<<<gadj, 256>>>(out);
}

// round 8
// speedup vs baseline: 1.1587x; 1.1587x over previous
#include <cuda_runtime.h>
#include <math.h>

#define N_NODES 10000
#define N_EDGES 320000
#define EPG 8            // edges per block per iteration

// output region offsets in floats
#define OFF_NODE_EMB   0L
#define OFF_EDGE_EMB   80000L
#define OFF_RECON_NODE 2640000L
#define OFF_RECON_EDGE 3280000L
#define OFF_ADJ        13520000L
#define OFF_COORD      113520000L

__device__ float g_A[N_NODES * 128];          // nf @ W1[0:64]  + b1
__device__ float g_B[N_NODES * 128];          // nf @ W1[64:128]
__device__ float g_hn[N_NODES * 128];         // relu(node layer-1)
__device__ float g_agg[N_NODES * 32];         // segment_sum(edge_out)
__device__ float g_emb[N_NODES * 8];          // node_emb copy for adj kernel
__device__ float g_r[N_NODES];                // ||node_emb||^2

// ---------------------------------------------------------------------------
__global__ void k_init(const float* __restrict__ coords, float* __restrict__ out) {
    int i = blockIdx.x * blockDim.x + threadIdx.x;
    if (i < N_NODES * 32) g_agg[i] = 0.f;
    if (i < N_NODES * 3)  out[OFF_COORD + i] = coords[i];
}

// ---------------------------------------------------------------------------
__global__ __launch_bounds__(128) void k_nodeproj(int which,
                                                  const float* __restrict__ nf,
                                                  const float* __restrict__ w,   // [64,128]
                                                  const float* __restrict__ b) {
    __shared__ float ws[64 * 128];
    __shared__ float xs[64];
    float* dst = which ? g_B : g_A;
    int tid = threadIdx.x;
    for (int i = tid; i < 64 * 128; i += 128) ws[i] = w[i];
    float bias = b ? b[tid] : 0.f;
    __syncthreads();
    for (int n = blockIdx.x; n < N_NODES; n += gridDim.x) {
        if (tid < 64) xs[tid] = nf[n * 64 + tid];
        __syncthreads();
        float acc = bias;
#pragma unroll
        for (int f = 0; f < 64; f++) acc = fmaf(xs[f], ws[f * 128 + tid], acc);
        dst[n * 128 + tid] = acc;
        __syncthreads();
    }
}

// ---------------------------------------------------------------------------
// K2: FUSED edge layers.  128 threads, EPG=8 edges per iteration.
// Thread = k (hidden unit); weights register-resident; activations via
// broadcast LDS.  Double-buffered stage smem -> 2 barriers/iter.
// Epilogue: smem-dot projection (no shuffle butterfly).
// ---------------------------------------------------------------------------
__global__ __launch_bounds__(128, 5) void k_edge_fused(
        const float* __restrict__ ew1,  // [161,128]
        const float* __restrict__ ew2, const float* __restrict__ eb2,
        const float* __restrict__ cw1, const float* __restrict__ cb1,
        const float* __restrict__ cw2,
        const float* __restrict__ few, const float* __restrict__ feb,
        const float* __restrict__ dew, const float* __restrict__ deb,
        const int* __restrict__ ei, const float* __restrict__ ea,
        const float* __restrict__ coords,
        float* __restrict__ out) {
    __shared__ __align__(16) float eas[2][EPG][32];
    __shared__ __align__(16) float hs[EPG][128];
    __shared__ __align__(16) float part[EPG][4][32];
    __shared__ __align__(16) float ovs[EPG][32];
    __shared__ __align__(16) float ers[EPG][8];
    __shared__ float geo[2][EPG][4];       // d0,d1,d2,radial
    __shared__ int   rc[2][EPG][2];
    __shared__ __align__(16) float s_fwT[10][36];   // [few|cw1] transposed
    __shared__ float s_b2[32], s_fcb[8], s_dew[256], s_deb[32], s_misc[4];

    int tid = threadIdx.x;
    int k = tid, kq = tid >> 5, j = tid & 31;

    if (tid < 32) { s_b2[tid] = eb2[tid]; s_deb[tid] = deb[tid]; }
    for (int x = tid; x < 320; x += 128) {       // s_fwT[r][j]
        int r = x >> 5, jj = x & 31;
        s_fwT[r][jj] = (r < 8) ? few[jj * 8 + r] : cw1[jj * 2 + (r - 8)];
    }
    for (int x = tid; x < 256; x += 128) s_dew[x] = dew[x];
    if (tid < 8)  s_fcb[tid] = feb[tid];
    if (tid == 0) { s_misc[0] = cb1[0]; s_misc[1] = cb1[1]; s_misc[2] = cw2[0]; s_misc[3] = cw2[1]; }

    float w1e[32];
#pragma unroll
    for (int t = 0; t < 32; t++) w1e[t] = ew1[(128 + t) * 128 + k];
    float w1r = ew1[160 * 128 + k];
    float w2r[32];
#pragma unroll
    for (int t = 0; t < 32; t++) w2r[t] = ew2[(kq * 32 + t) * 32 + j];

    const long stride = (long)gridDim.x * EPG;
    long base = (long)blockIdx.x * EPG;
    const int ie = tid >> 4, c2 = (tid & 15) * 2;
    int pb = 0;

    // ---- initial stage into buffer 0 ----
    if (k < EPG) {
        long e = base + k;
        int r = ei[e], c = ei[N_EDGES + e];
        rc[0][k][0] = r; rc[0][k][1] = c;
        float d0 = coords[r * 3 + 0] - coords[c * 3 + 0];
        float d1 = coords[r * 3 + 1] - coords[c * 3 + 1];
        float d2 = coords[r * 3 + 2] - coords[c * 3 + 2];
        geo[0][k][0] = d0; geo[0][k][1] = d1; geo[0][k][2] = d2;
        geo[0][k][3] = d0 * d0 + d1 * d1 + d2 * d2;
    }
    {
        float2 v = *(const float2*)(ea + (base + ie) * 32 + c2);
        eas[0][ie][c2] = v.x; eas[0][ie][c2 + 1] = v.y;
    }
    __syncthreads();

    for (; base < N_EDGES; base += stride) {
        long nbase = base + stride;
        bool has_next = nbase < N_EDGES;

        // ---- prefetch ONLY ea + edge indices into registers ----
        float2 pf_ea = make_float2(0.f, 0.f);
        int pf_r = 0, pf_c = 0;
        if (has_next) {
            pf_ea = *(const float2*)(ea + (nbase + ie) * 32 + c2);
            if (k < EPG) {
                pf_r = ei[nbase + k]; pf_c = ei[N_EDGES + nbase + k];
            }
        }

        // ---- layer 1 (reads stage buffer pb) ----
        float h[EPG];
#pragma unroll
        for (int i = 0; i < EPG; i++) {
            int r = rc[pb][i][0], c = rc[pb][i][1];
            h[i] = g_A[(long)r * 128 + k] + g_B[(long)c * 128 + k]
                 + geo[pb][i][3] * w1r;
        }
#pragma unroll
        for (int i = 0; i < EPG; i++) {
            const float4* ev = (const float4*)eas[pb][i];
            float acc = 0.f;
#pragma unroll
            for (int q = 0; q < 8; q++) {
                float4 v = ev[q];
                acc = fmaf(v.x, w1e[q * 4 + 0], acc);
                acc = fmaf(v.y, w1e[q * 4 + 1], acc);
                acc = fmaf(v.z, w1e[q * 4 + 2], acc);
                acc = fmaf(v.w, w1e[q * 4 + 3], acc);
            }
            hs[i][k] = fmaxf(h[i] + acc, 0.f);
        }
        __syncthreads();   // hs ready; ALL warps finished prev epilogue

        // ---- write next stage into buffer pb^1 (coords loaded here,
        //      latency hidden behind layer 2) ----
        if (has_next) {
            eas[pb ^ 1][ie][c2] = pf_ea.x; eas[pb ^ 1][ie][c2 + 1] = pf_ea.y;
            if (k < EPG) {
                rc[pb ^ 1][k][0] = pf_r; rc[pb ^ 1][k][1] = pf_c;
                float d0 = coords[pf_r * 3 + 0] - coords[pf_c * 3 + 0];
                float d1 = coords[pf_r * 3 + 1] - coords[pf_c * 3 + 1];
                float d2 = coords[pf_r * 3 + 2] - coords[pf_c * 3 + 2];
                geo[pb ^ 1][k][0] = d0; geo[pb ^ 1][k][1] = d1;
                geo[pb ^ 1][k][2] = d2;
                geo[pb ^ 1][k][3] = d0 * d0 + d1 * d1 + d2 * d2;
            }
        }

        // ---- layer 2: warp kq reduces its 32-k slice for all 8 edges ----
#pragma unroll
        for (int i = 0; i < EPG; i++) {
            const float4* hv = (const float4*)(hs[i] + kq * 32);
            float p = 0.f;
#pragma unroll
            for (int q = 0; q < 8; q++) {
                float4 v = hv[q];
                p = fmaf(v.x, w2r[q * 4 + 0], p);
                p = fmaf(v.y, w2r[q * 4 + 1], p);
                p = fmaf(v.z, w2r[q * 4 + 2], p);
                p = fmaf(v.w, w2r[q * 4 + 3], p);
            }
            part[i][kq][j] = p;
        }
        __syncthreads();   // part ready; next stage visible

        // ---- epilogue: warp kq handles edges kq*2, kq*2+1 ----
#pragma unroll
        for (int s = 0; s < 2; s++) {
            int i = kq * 2 + s;
            long e = base + i;
            int row = rc[pb][i][0];
            float ov = part[i][0][j] + part[i][1][j] + part[i][2][j]
                     + part[i][3][j] + s_b2[j];
            atomicAdd(&g_agg[row * 32 + j], ov);
            ovs[i][j] = ov;
            __syncwarp();
            // 10-lane projection: er[0:8] = ov @ few, acc[8:10] = ov @ cw1
            float acc = 0.f;
            if (j < 10) {
                const float4* ovv = (const float4*)ovs[i];
#pragma unroll
                for (int q = 0; q < 8; q++) {
                    float4 v = ovv[q];
                    acc = fmaf(v.x, s_fwT[j][q * 4 + 0], acc);
                    acc = fmaf(v.y, s_fwT[j][q * 4 + 1], acc);
                    acc = fmaf(v.z, s_fwT[j][q * 4 + 2], acc);
                    acc = fmaf(v.w, s_fwT[j][q * 4 + 3], acc);
                }
            }
            if (j < 8) {
                float er = acc + s_fcb[j];
                out[OFF_EDGE_EMB + e * 8 + j] = er;
                ers[i][j] = er;
            }
            float q8 = __shfl_sync(0xffffffffu, acc, 8);
            float q9 = __shfl_sync(0xffffffffu, acc, 9);
            __syncwarp();   // ers visible to all lanes
            float4 e0 = ((const float4*)ers[i])[0];
            float4 e1 = ((const float4*)ers[i])[1];
            float rec = s_deb[j];
            rec = fmaf(e0.x, s_dew[0 * 32 + j], rec);
            rec = fmaf(e0.y, s_dew[1 * 32 + j], rec);
            rec = fmaf(e0.z, s_dew[2 * 32 + j], rec);
            rec = fmaf(e0.w, s_dew[3 * 32 + j], rec);
            rec = fmaf(e1.x, s_dew[4 * 32 + j], rec);
            rec = fmaf(e1.y, s_dew[5 * 32 + j], rec);
            rec = fmaf(e1.z, s_dew[6 * 32 + j], rec);
            rec = fmaf(e1.w, s_dew[7 * 32 + j], rec);
            out[OFF_RECON_EDGE + e * 32 + j] = rec;
            if (j < 3) {
                float wz = fmaxf(q8 + s_misc[0], 0.f) * s_misc[2] +
                           fmaxf(q9 + s_misc[1], 0.f) * s_misc[3];
                float inv = 1.0f / (sqrtf(geo[pb][i][3]) + 1.0f);
                atomicAdd(out + OFF_COORD + row * 3 + j, geo[pb][i][j] * inv * wz);
            }
        }
        pb ^= 1;
    }
}

// ---------------------------------------------------------------------------
__global__ __launch_bounds__(256) void k_node_h(const float* __restrict__ nw1,  // [99,128]
                                                const float* __restrict__ nb1,
                                                const float* __restrict__ nf,
                                                const float* __restrict__ outc) {
    int tid = threadIdx.x;
    int k = tid & 127, slot = tid >> 7, lane = tid & 31;
    float bias = nb1[k];
    float wc0 = nw1[96 * 128 + k], wc1 = nw1[97 * 128 + k], wc2 = nw1[98 * 128 + k];
    for (int n0 = blockIdx.x * 2; n0 < N_NODES; n0 += gridDim.x * 2) {
        int n = n0 + slot;
        float xa = nf[n * 64 + lane];
        float xb = nf[n * 64 + 32 + lane];
        float xc = g_agg[n * 32 + lane];
        float h = bias;
#pragma unroll
        for (int t = 0; t < 32; t++)
            h = fmaf(__shfl_sync(0xffffffffu, xa, t), __ldg(nw1 + t * 128 + k), h);
#pragma unroll
        for (int t = 0; t < 32; t++)
            h = fmaf(__shfl_sync(0xffffffffu, xb, t), __ldg(nw1 + (32 + t) * 128 + k), h);
#pragma unroll
        for (int t = 0; t < 32; t++)
            h = fmaf(__shfl_sync(0xffffffffu, xc, t), __ldg(nw1 + (64 + t) * 128 + k), h);
        h = fmaf(outc[n * 3 + 0], wc0, h);
        h = fmaf(outc[n * 3 + 1], wc1, h);
        h = fmaf(outc[n * 3 + 2], wc2, h);
        g_hn[n * 128 + k] = fmaxf(h, 0.f);
    }
}

// ---------------------------------------------------------------------------
__global__ __launch_bounds__(256) void k_node_out(
        const float* __restrict__ nw2, const float* __restrict__ nb2,
        const float* __restrict__ fnw, const float* __restrict__ fnb,
        const float* __restrict__ dnw, const float* __restrict__ dnb,
        float* __restrict__ out) {
    __shared__ float ps[4][2][8];
    int tid = threadIdx.x;
    int slot = tid >> 6, jj = tid & 63, half = (tid >> 5) & 1, lane = tid & 31;
    float bias = nb2[jj];
    for (int n0 = blockIdx.x * 4; n0 < N_NODES; n0 += gridDim.x * 4) {
        int n = n0 + slot;
        const float* hrow = g_hn + n * 128;
        float acc = bias;
#pragma unroll 8
        for (int kk = 0; kk < 128; kk++)
            acc = fmaf(__ldg(hrow + kk), __ldg(nw2 + kk * 64 + jj), acc);
        float p[8];
#pragma unroll
        for (int r = 0; r < 8; r++) p[r] = acc * __ldg(fnw + jj * 8 + r);
#pragma unroll
        for (int off = 16; off > 0; off >>= 1) {
#pragma unroll
            for (int r = 0; r < 8; r++) p[r] += __shfl_xor_sync(0xffffffffu, p[r], off);
        }
        if (lane == 0) {
#pragma unroll
            for (int r = 0; r < 8; r++) ps[slot][half][r] = p[r];
        }
        __syncthreads();
        float er[8];
#pragma unroll
        for (int r = 0; r < 8; r++) er[r] = ps[slot][0][r] + ps[slot][1][r] + __ldg(fnb + r);
        if (jj == 0) {
            float4 v0 = make_float4(er[0], er[1], er[2], er[3]);
            float4 v1 = make_float4(er[4], er[5], er[6], er[7]);
            ((float4*)(out + OFF_NODE_EMB + (long)n * 8))[0] = v0;
            ((float4*)(out + OFF_NODE_EMB + (long)n * 8))[1] = v1;
            ((float4*)(g_emb + n * 8))[0] = v0;
            ((float4*)(g_emb + n * 8))[1] = v1;
            float rr = 0.f;
#pragma unroll
            for (int r = 0; r < 8; r++) rr = fmaf(er[r], er[r], rr);
            g_r[n] = rr;
        }
        float rec = __ldg(dnb + jj);
#pragma unroll
        for (int r = 0; r < 8; r++) rec = fmaf(er[r], __ldg(dnw + r * 64 + jj), rec);
        out[OFF_RECON_NODE + (long)n * 64 + jj] = rec;
        __syncthreads();
    }
}

// ---------------------------------------------------------------------------
__global__ __launch_bounds__(256) void k_adj(float* __restrict__ out) {
    int tid = threadIdx.x;
    int j0 = blockIdx.x * 1024 + tid * 4;
    float ej[4][8], rj[4];
#pragma unroll
    for (int q = 0; q < 4; q++) {
        int jx = j0 + q;
        if (jx < N_NODES) {
            float4 a = ((const float4*)(g_emb + jx * 8))[0];
            float4 b = ((const float4*)(g_emb + jx * 8))[1];
            ej[q][0] = a.x; ej[q][1] = a.y; ej[q][2] = a.z; ej[q][3] = a.w;
            ej[q][4] = b.x; ej[q][5] = b.y; ej[q][6] = b.z; ej[q][7] = b.w;
            rj[q] = g_r[jx];
        } else {
#pragma unroll
            for (int r = 0; r < 8; r++) ej[q][r] = 0.f;
            rj[q] = 0.f;
        }
    }
    int ibase = blockIdx.y * 16;
    for (int ii = 0; ii < 16; ii++) {
        int i = ibase + ii;
        float4 a = ((const float4*)(g_emb + i * 8))[0];
        float4 b = ((const float4*)(g_emb + i * 8))[1];
        float eiv[8] = {a.x, a.y, a.z, a.w, b.x, b.y, b.z, b.w};
        float ri = g_r[i];
        float res[4];
#pragma unroll
        for (int q = 0; q < 4; q++) {
            float dot = 0.f;
#pragma unroll
            for (int r = 0; r < 8; r++) dot = fmaf(eiv[r], ej[q][r], dot);
            float d2 = ri + rj[q] - 2.f * dot;
            // sigmoid(x) = 0.5*tanh(x/2)+0.5, single MUFU
            float x = 3.f * d2 - 1.f;
            float t;
            asm("tanh.approx.f32 %0, %1;" : "=f"(t) : "f"(x * 0.5f));
            float v = fmaf(0.5f, t, 0.5f);
            res[q] = (j0 + q == i) ? 0.f : v;
        }
        if (j0 < N_NODES) {
            __stcs((float4*)(out + OFF_ADJ + (long)i * N_NODES + j0),
                   make_float4(res[0], res[1], res[2], res[3]));
        }
    }
}

// ---------------------------------------------------------------------------
extern "C" void kernel_launch(void* const* d_in, const int* in_sizes, int n_in,
                              void* d_out, int out_size) {
    const float* nf     = (const float*)d_in[0];
    const int*   ei     = (const int*)  d_in[1];
    const float* ea     = (const float*)d_in[2];
    const float* coords = (const float*)d_in[3];
    const float* ew1    = (const float*)d_in[4];
    const float* eb1    = (const float*)d_in[5];
    const float* ew2    = (const float*)d_in[6];
    const float* eb2    = (const float*)d_in[7];
    const float* cw1    = (const float*)d_in[8];
    const float* cb1    = (const float*)d_in[9];
    const float* cw2    = (const float*)d_in[10];
    const float* nw1    = (const float*)d_in[11];
    const float* nb1    = (const float*)d_in[12];
    const float* nw2    = (const float*)d_in[13];
    const float* nb2    = (const float*)d_in[14];
    const float* fnw    = (const float*)d_in[15];
    const float* fnb    = (const float*)d_in[16];
    const float* few    = (const float*)d_in[17];
    const float* feb    = (const float*)d_in[18];
    const float* dnw    = (const float*)d_in[19];
    const float* dnb    = (const float*)d_in[20];
    const float* dew    = (const float*)d_in[21];
    const float* deb    = (const float*)d_in[22];
    float* out = (float*)d_out;

    k_init<<<(N_NODES * 32 + 255) / 256, 256>>>(coords, out);
    k_nodeproj<<<592, 128>>>(0, nf, ew1, eb1);
    k_nodeproj<<<592, 128>>>(1, nf, ew1 + 64 * 128, 0);
    k_edge_fused<<<740, 128>>>(ew1, ew2, eb2, cw1, cb1, cw2, few, feb, dew, deb,
                               ei, ea, coords, out);
    k_node_h<<<592, 256>>>(nw1, nb1, nf, out + OFF_COORD);
    k_node_out<<<592, 256>>>(nw2, nb2, fnw, fnb, dnw, dnb, out);
    dim3 gadj((N_NODES + 1023) / 1024, N_NODES / 16);
    k_adj<<<gadj, 256>>>(out);
}